// round 2
// baseline (speedup 1.0000x reference)
#include <cuda_runtime.h>
#include <cuda_fp16.h>
#include <cstdint>

#define N_NODES 100000
#define N_EDGES 1200000
#define D_NODE 64
#define HID 128
#define SW 136            // smem row stride in halfs (pad 8 -> conflict-free mma frag loads)
#define TILE_M 128

// ---------------- device scratch (no allocs allowed) ----------------
__device__ float g_agg[(size_t)N_NODES * 64];          // 25.6 MB
// packed fp16 weight fragments (hi + lo split): [kt][ntile][lane] -> uint2 (b0,b1 of m16n8k16 B frag)
__device__ uint2 g_W0h[8 * 16 * 32], g_W0l[8 * 16 * 32];
__device__ uint2 g_W1h[8 * 16 * 32], g_W1l[8 * 16 * 32];
__device__ uint2 g_W2h[8 *  8 * 32], g_W2l[8 *  8 * 32];

// ---------------- helpers ----------------
__device__ __forceinline__ uint32_t f2_to_h2(float a, float b) {
    __half ha = __float2half_rn(a), hb = __float2half_rn(b);
    return (uint32_t)__half_as_ushort(ha) | ((uint32_t)__half_as_ushort(hb) << 16);
}
__device__ __forceinline__ float h_res(float a) {
    return a - __half2float(__float2half_rn(a));
}

__device__ __forceinline__ void mma16816(float c[4], const uint32_t a[4], uint2 b) {
    asm volatile(
        "mma.sync.aligned.m16n8k16.row.col.f32.f16.f16.f32 "
        "{%0,%1,%2,%3},{%4,%5,%6,%7},{%8,%9},{%0,%1,%2,%3};"
        : "+f"(c[0]), "+f"(c[1]), "+f"(c[2]), "+f"(c[3])
        : "r"(a[0]), "r"(a[1]), "r"(a[2]), "r"(a[3]), "r"(b.x), "r"(b.y));
}

// ---------------- weight pack: fp32 -> (hi, lo) fp16 mma B fragments ----------------
__global__ void pack_w_kernel(const float* __restrict__ W0,
                              const float* __restrict__ W1,
                              const float* __restrict__ W2) {
    int t = blockIdx.x * blockDim.x + threadIdx.x;
    if (t >= 10240) return;
    const float* W; uint2 *ph, *pl; int NT, Ncols, idx;
    if (t < 4096)       { W = W0; ph = g_W0h; pl = g_W0l; NT = 16; Ncols = 128; idx = t; }
    else if (t < 8192)  { W = W1; ph = g_W1h; pl = g_W1l; NT = 16; Ncols = 128; idx = t - 4096; }
    else                { W = W2; ph = g_W2h; pl = g_W2l; NT = 8;  Ncols = 64;  idx = t - 8192; }
    int lane = idx & 31, tile = idx >> 5;
    int nt = tile % NT, kt = tile / NT;
    int k0 = kt * 16 + (lane & 3) * 2;
    int n  = nt * 8  + (lane >> 2);
    float w00 = W[(k0    ) * Ncols + n];
    float w01 = W[(k0 + 1) * Ncols + n];
    float w10 = W[(k0 + 8) * Ncols + n];
    float w11 = W[(k0 + 9) * Ncols + n];
    ph[idx] = make_uint2(f2_to_h2(w00, w01), f2_to_h2(w10, w11));
    pl[idx] = make_uint2(f2_to_h2(h_res(w00), h_res(w01)), f2_to_h2(h_res(w10), h_res(w11)));
}

// ---------------- scatter: segment-sum of edge_attr by dest via red.v4 ----------------
__global__ void scatter_kernel(const float4* __restrict__ ea,
                               const int* __restrict__ ei, int n_edges) {
    // dtype detect: int64 layout => odd int32 words of row-0 values (<100000) are zero
    bool is64 = (ei[1] == 0) & (ei[3] == 0) & (ei[5] == 0) & (ei[7] == 0);
    int i = blockIdx.x * blockDim.x + threadIdx.x;
    if (i >= n_edges * 16) return;
    int e = i >> 4, c = i & 15;
    long long d;
    if (is64) d = ((const long long*)ei)[n_edges + e];
    else      d = (long long)ei[n_edges + e];
    float4 v = __ldg(&ea[i]);
    float* p = g_agg + d * 64 + c * 4;
    asm volatile("red.global.add.v4.f32 [%0], {%1, %2, %3, %4};"
                 :: "l"(p), "f"(v.x), "f"(v.y), "f"(v.z), "f"(v.w)
                 : "memory");
}

// ---------------- fused MLP + LayerNorm + residual ----------------
template <int NTW, int NTT>
__device__ __forceinline__ void gemm_layer(const __half* sh_hi, const __half* sh_lo,
                                           const uint2* __restrict__ Bh,
                                           const uint2* __restrict__ Bl,
                                           int warp_m, int ntile0, int lane,
                                           float acc[2][NTW][4]) {
#pragma unroll
    for (int mt = 0; mt < 2; mt++)
#pragma unroll
        for (int nt = 0; nt < NTW; nt++)
#pragma unroll
            for (int q = 0; q < 4; q++) acc[mt][nt][q] = 0.f;

    int rA  = warp_m + (lane >> 2);
    int cAq = (lane & 3) * 2;
#pragma unroll
    for (int kt = 0; kt < 8; kt++) {
        uint32_t Ah[2][4], Al[2][4];
        int cA = kt * 16 + cAq;
#pragma unroll
        for (int mt = 0; mt < 2; mt++) {
            int r = rA + mt * 16;
            Ah[mt][0] = *(const uint32_t*)(sh_hi + r * SW + cA);
            Ah[mt][1] = *(const uint32_t*)(sh_hi + (r + 8) * SW + cA);
            Ah[mt][2] = *(const uint32_t*)(sh_hi + r * SW + cA + 8);
            Ah[mt][3] = *(const uint32_t*)(sh_hi + (r + 8) * SW + cA + 8);
            Al[mt][0] = *(const uint32_t*)(sh_lo + r * SW + cA);
            Al[mt][1] = *(const uint32_t*)(sh_lo + (r + 8) * SW + cA);
            Al[mt][2] = *(const uint32_t*)(sh_lo + r * SW + cA + 8);
            Al[mt][3] = *(const uint32_t*)(sh_lo + (r + 8) * SW + cA + 8);
        }
#pragma unroll
        for (int nt = 0; nt < NTW; nt++) {
            int bi = (kt * NTT + ntile0 + nt) * 32 + lane;
            uint2 bh = __ldg(&Bh[bi]);
            uint2 bl = __ldg(&Bl[bi]);
#pragma unroll
            for (int mt = 0; mt < 2; mt++) {
                mma16816(acc[mt][nt], Ah[mt], bh);   // hi * hi
                mma16816(acc[mt][nt], Al[mt], bh);   // lo * hi
                mma16816(acc[mt][nt], Ah[mt], bl);   // hi * lo
            }
        }
    }
}

template <int NTW>
__device__ __forceinline__ void epilogue_relu(float acc[2][NTW][4],
                                              const float* __restrict__ bias,
                                              int warp_m, int ntile0, int lane,
                                              __half* sh_hi, __half* sh_lo) {
    __syncthreads();  // all warps done reading previous h
#pragma unroll
    for (int mt = 0; mt < 2; mt++)
#pragma unroll
        for (int nt = 0; nt < NTW; nt++) {
            int r0 = warp_m + mt * 16 + (lane >> 2);
            int c  = (ntile0 + nt) * 8 + (lane & 3) * 2;
            float bx = __ldg(&bias[c]), by = __ldg(&bias[c + 1]);
            float v0 = fmaxf(acc[mt][nt][0] + bx, 0.f);
            float v1 = fmaxf(acc[mt][nt][1] + by, 0.f);
            float v2 = fmaxf(acc[mt][nt][2] + bx, 0.f);
            float v3 = fmaxf(acc[mt][nt][3] + by, 0.f);
            *(uint32_t*)(sh_hi + r0 * SW + c)       = f2_to_h2(v0, v1);
            *(uint32_t*)(sh_lo + r0 * SW + c)       = f2_to_h2(h_res(v0), h_res(v1));
            *(uint32_t*)(sh_hi + (r0 + 8) * SW + c) = f2_to_h2(v2, v3);
            *(uint32_t*)(sh_lo + (r0 + 8) * SW + c) = f2_to_h2(h_res(v2), h_res(v3));
        }
    __syncthreads();
}

__global__ __launch_bounds__(256) void mlp_kernel(
    const float* __restrict__ x,
    const float* __restrict__ b0, const float* __restrict__ b1,
    const float* __restrict__ b2,
    const float* __restrict__ lng, const float* __restrict__ lnb,
    float* __restrict__ out) {
    extern __shared__ __align__(16) unsigned char smem_raw[];
    __half* sh_hi = (__half*)smem_raw;
    __half* sh_lo = sh_hi + 128 * SW;
    float*  s_stat = (float*)(sh_lo + 128 * SW);  // mu[128], rstd[128]

    int tid = threadIdx.x, lane = tid & 31, w = tid >> 5;
    int block0 = blockIdx.x * TILE_M;

    // stage h0 = [x | agg] as fp16 hi/lo
    for (int i = tid; i < 128 * 128; i += 256) {
        int r = i >> 7, c = i & 127;
        int nm = block0 + r;
        float v = 0.f;
        if (nm < N_NODES)
            v = (c < 64) ? __ldg(&x[nm * 64 + c]) : g_agg[nm * 64 + (c - 64)];
        __half hi = __float2half_rn(v);
        sh_hi[r * SW + c] = hi;
        sh_lo[r * SW + c] = __float2half_rn(v - __half2float(hi));
    }
    __syncthreads();

    int warp_m = (w & 3) * 32;
    int wn = w >> 2;  // 0..1

    {
        float acc[2][8][4];
        gemm_layer<8, 16>(sh_hi, sh_lo, g_W0h, g_W0l, warp_m, wn * 8, lane, acc);
        epilogue_relu<8>(acc, b0, warp_m, wn * 8, lane, sh_hi, sh_lo);
        gemm_layer<8, 16>(sh_hi, sh_lo, g_W1h, g_W1l, warp_m, wn * 8, lane, acc);
        epilogue_relu<8>(acc, b1, warp_m, wn * 8, lane, sh_hi, sh_lo);
    }

    // layer 2: N = 64
    float* sy = (float*)smem_raw;  // 128 x 65 fp32 overlays sh_hi (written post-sync)
    {
        float acc2[2][4][4];
        gemm_layer<4, 8>(sh_hi, sh_lo, g_W2h, g_W2l, warp_m, wn * 4, lane, acc2);
        __syncthreads();  // everyone done reading h1 before overlay write
#pragma unroll
        for (int mt = 0; mt < 2; mt++)
#pragma unroll
            for (int nt = 0; nt < 4; nt++) {
                int r0 = warp_m + mt * 16 + (lane >> 2);
                int c  = (wn * 4 + nt) * 8 + (lane & 3) * 2;
                float bx = __ldg(&b2[c]), by = __ldg(&b2[c + 1]);
                sy[r0 * 65 + c]           = acc2[mt][nt][0] + bx;
                sy[r0 * 65 + c + 1]       = acc2[mt][nt][1] + by;
                sy[(r0 + 8) * 65 + c]     = acc2[mt][nt][2] + bx;
                sy[(r0 + 8) * 65 + c + 1] = acc2[mt][nt][3] + by;
            }
    }
    __syncthreads();

    // per-row LayerNorm stats
    if (tid < 128) {
        const float* row = sy + tid * 65;
        float s = 0.f, ss = 0.f;
#pragma unroll
        for (int c = 0; c < 64; c++) { float v = row[c]; s += v; ss += v * v; }
        float mu = s * 0.015625f;
        float var = ss * 0.015625f - mu * mu;
        s_stat[tid]       = mu;
        s_stat[128 + tid] = rsqrtf(var + 1e-5f);
    }
    __syncthreads();

    // coalesced normalize + residual + store
    for (int i = tid; i < 128 * 64; i += 256) {
        int r = i >> 6, c = i & 63;
        int nm = block0 + r;
        if (nm < N_NODES) {
            float v = sy[r * 65 + c];
            float res = (v - s_stat[r]) * s_stat[128 + r] * __ldg(&lng[c]) +
                        __ldg(&lnb[c]) + __ldg(&x[nm * 64 + c]);
            out[nm * 64 + c] = res;
        }
    }
}

// ---------------- launch ----------------
extern "C" void kernel_launch(void* const* d_in, const int* in_sizes, int n_in,
                              void* d_out, int out_size) {
    const float* x  = (const float*)d_in[0];
    const int*   ei = (const int*)d_in[1];   // int32 or int64; detected on device
    const float* ea = (const float*)d_in[2];
    const float* W0 = (const float*)d_in[3];
    const float* b0 = (const float*)d_in[4];
    const float* W1 = (const float*)d_in[5];
    const float* b1 = (const float*)d_in[6];
    const float* W2 = (const float*)d_in[7];
    const float* b2 = (const float*)d_in[8];
    const float* lg = (const float*)d_in[9];
    const float* lb = (const float*)d_in[10];
    float* out = (float*)d_out;

    void* aggp = nullptr;
    cudaGetSymbolAddress(&aggp, g_agg);
    cudaMemsetAsync(aggp, 0, sizeof(float) * (size_t)N_NODES * 64, 0);

    pack_w_kernel<<<40, 256>>>(W0, W1, W2);

    int items = N_EDGES * 16;
    scatter_kernel<<<(items + 255) / 256, 256>>>((const float4*)ea, ei, N_EDGES);

    const int smem_bytes = 2 * 128 * SW * (int)sizeof(__half) + 256 * (int)sizeof(float);
    cudaFuncSetAttribute(mlp_kernel, cudaFuncAttributeMaxDynamicSharedMemorySize, smem_bytes);
    int grid = (N_NODES + TILE_M - 1) / TILE_M;
    mlp_kernel<<<grid, 256, smem_bytes>>>(x, b0, b1, b2, lg, lb, out);
}